// round 9
// baseline (speedup 1.0000x reference)
#include <cuda_runtime.h>

// Fixed problem shape — kernel_launch is a pure function of the data pointers.
#define N_NODES 100000
#define N_EDGES 1600000
#define DIM     128
#define D4      32          // DIM/4
#define TILE_M  32
#define KCHUNK  32          // K rows of W staged per smem chunk (16 KB)
#define OUTD    5

// ---------------- scratch (device globals; referenced ONLY in device code!) ----
// NOTE: passing these symbols as kernel arguments from host code passes the
// HOST shadow address (valid via ATS on GB300!) -> two disjoint buffers and
// cross-call accumulation. All kernels below reference them directly.
__device__ __align__(16) float g_agg1[(size_t)N_NODES * DIM];
__device__ __align__(16) float g_agg2[(size_t)N_NODES * DIM];
__device__ __align__(16) float g_h1  [(size_t)N_NODES * DIM];
__device__ int   g_cnt [N_NODES];
__device__ float g_invc[N_NODES];

// ---------------- zero agg buffers + counts ----------------
__global__ void __launch_bounds__(256) zero_kernel() {
    int i = blockIdx.x * 256 + threadIdx.x;
    float4 z = make_float4(0.f, 0.f, 0.f, 0.f);
    if (i < N_NODES * D4) {
        reinterpret_cast<float4*>(g_agg1)[i] = z;
        reinterpret_cast<float4*>(g_agg2)[i] = z;
    }
    if (i < N_NODES) g_cnt[i] = 0;
}

// ---------------- scatter-add: one warp per edge, float4 atomics ----------------
// FIRST=true : feat = x (param), agg = g_agg1, also counts degrees.
// FIRST=false: feat = g_h1 (device symbol), agg = g_agg2.
template <bool FIRST>
__global__ void __launch_bounds__(256) scatter_kernel(
    const float4* __restrict__ xfeat,
    const int*    __restrict__ src,
    const int*    __restrict__ tgt)
{
    int gid  = blockIdx.x * 256 + threadIdx.x;
    int e    = gid >> 5;
    int lane = gid & 31;
    if (e >= N_EDGES) return;
    int s = __ldg(src + e);
    int t = __ldg(tgt + e);
    const float4* feat = FIRST ? xfeat
                               : reinterpret_cast<const float4*>(g_h1);
    float4* agg = FIRST ? reinterpret_cast<float4*>(g_agg1)
                        : reinterpret_cast<float4*>(g_agg2);
    float4 v = feat[(size_t)s * D4 + lane];
    atomicAdd(&agg[(size_t)t * D4 + lane], v);   // red.global.add.v4.f32 (sm_90+)
    if (FIRST && lane == 0) atomicAdd(&g_cnt[t], 1);
}

// ---------------- 1 / max(cnt,1) ----------------
__global__ void __launch_bounds__(256) invcnt_kernel() {
    int i = blockIdx.x * 256 + threadIdx.x;
    if (i < N_NODES) {
        int c = g_cnt[i];
        if (c < 1) c = 1;
        g_invc[i] = 1.0f / (float)c;
    }
}

// ---------------- GEMM layer 1: g_h1 = relu((x + agg1*invc) @ W1 + b1) --------
// 256 threads, TILE_M=32 node rows, full 128 output cols.
// Static smem: W chunk 32x128 (16KB) + input tile 32x128 (16KB) = 32KB.
__global__ void __launch_bounds__(256) gemm_relu_kernel(
    const float4* __restrict__ xin,
    const float*  __restrict__ W,
    const float*  __restrict__ b)
{
    __shared__ float  sW[KCHUNK * DIM];      // 16 KB
    __shared__ float4 sIn[TILE_M * D4];      // 16 KB

    const float4* agg = reinterpret_cast<const float4*>(g_agg1);
    int row0 = blockIdx.x * TILE_M;

    #pragma unroll
    for (int i = threadIdx.x; i < TILE_M * D4; i += 256) {
        int r = i >> 5, c = i & 31;
        int node = row0 + r;
        float ic = g_invc[node];
        float4 xv = xin[(size_t)node * D4 + c];
        float4 av = agg[(size_t)node * D4 + c];
        sIn[i] = make_float4(fmaf(av.x, ic, xv.x), fmaf(av.y, ic, xv.y),
                             fmaf(av.z, ic, xv.z), fmaf(av.w, ic, xv.w));
    }

    int tn   = threadIdx.x & 127;
    int half = threadIdx.x >> 7;
    float acc[16];
    #pragma unroll
    for (int m = 0; m < 16; m++) acc[m] = 0.f;

    float4* sW4 = reinterpret_cast<float4*>(sW);
    #pragma unroll 1
    for (int kc = 0; kc < DIM / KCHUNK; kc++) {
        __syncthreads();                     // sW reuse / sIn ready (first iter)
        const float4* Wsrc = reinterpret_cast<const float4*>(W + kc * KCHUNK * DIM);
        #pragma unroll
        for (int i = threadIdx.x; i < KCHUNK * D4; i += 256) sW4[i] = Wsrc[i];
        __syncthreads();

        #pragma unroll 4
        for (int k4 = 0; k4 < KCHUNK / 4; k4++) {
            float w0 = sW[(k4 * 4 + 0) * DIM + tn];
            float w1 = sW[(k4 * 4 + 1) * DIM + tn];
            float w2 = sW[(k4 * 4 + 2) * DIM + tn];
            float w3 = sW[(k4 * 4 + 3) * DIM + tn];
            #pragma unroll
            for (int m = 0; m < 16; m++) {
                float4 xv = sIn[(half * 16 + m) * D4 + kc * (KCHUNK / 4) + k4];
                acc[m] = fmaf(xv.x, w0, acc[m]);
                acc[m] = fmaf(xv.y, w1, acc[m]);
                acc[m] = fmaf(xv.z, w2, acc[m]);
                acc[m] = fmaf(xv.w, w3, acc[m]);
            }
        }
    }

    float bias = __ldg(b + tn);
    #pragma unroll
    for (int m = 0; m < 16; m++) {
        int node = row0 + half * 16 + m;
        g_h1[(size_t)node * DIM + tn] = fmaxf(acc[m] + bias, 0.f);
    }
}

// ---------------- GEMM layer 2 fused with projection ----------------
// h2 = relu((g_h1 + agg2*invc) @ W2 + b2) kept in smem; out = h2 @ Wp + bp.
__global__ void __launch_bounds__(256) gemm_proj_kernel(
    const float*  __restrict__ W,
    const float*  __restrict__ b,
    const float*  __restrict__ Wp,
    const float*  __restrict__ bp,
    float*        __restrict__ out)
{
    __shared__ float  sW[KCHUNK * DIM];      // 16 KB
    __shared__ float4 sIn[TILE_M * D4];      // 16 KB (reused as h2 tile)

    const float4* xin = reinterpret_cast<const float4*>(g_h1);
    const float4* agg = reinterpret_cast<const float4*>(g_agg2);
    int row0 = blockIdx.x * TILE_M;

    #pragma unroll
    for (int i = threadIdx.x; i < TILE_M * D4; i += 256) {
        int r = i >> 5, c = i & 31;
        int node = row0 + r;
        float ic = g_invc[node];
        float4 xv = xin[(size_t)node * D4 + c];
        float4 av = agg[(size_t)node * D4 + c];
        sIn[i] = make_float4(fmaf(av.x, ic, xv.x), fmaf(av.y, ic, xv.y),
                             fmaf(av.z, ic, xv.z), fmaf(av.w, ic, xv.w));
    }

    int tn   = threadIdx.x & 127;
    int half = threadIdx.x >> 7;
    float acc[16];
    #pragma unroll
    for (int m = 0; m < 16; m++) acc[m] = 0.f;

    float4* sW4 = reinterpret_cast<float4*>(sW);
    #pragma unroll 1
    for (int kc = 0; kc < DIM / KCHUNK; kc++) {
        __syncthreads();
        const float4* Wsrc = reinterpret_cast<const float4*>(W + kc * KCHUNK * DIM);
        #pragma unroll
        for (int i = threadIdx.x; i < KCHUNK * D4; i += 256) sW4[i] = Wsrc[i];
        __syncthreads();

        #pragma unroll 4
        for (int k4 = 0; k4 < KCHUNK / 4; k4++) {
            float w0 = sW[(k4 * 4 + 0) * DIM + tn];
            float w1 = sW[(k4 * 4 + 1) * DIM + tn];
            float w2 = sW[(k4 * 4 + 2) * DIM + tn];
            float w3 = sW[(k4 * 4 + 3) * DIM + tn];
            #pragma unroll
            for (int m = 0; m < 16; m++) {
                float4 xv = sIn[(half * 16 + m) * D4 + kc * (KCHUNK / 4) + k4];
                acc[m] = fmaf(xv.x, w0, acc[m]);
                acc[m] = fmaf(xv.y, w1, acc[m]);
                acc[m] = fmaf(xv.z, w2, acc[m]);
                acc[m] = fmaf(xv.w, w3, acc[m]);
            }
        }
    }

    float bias = __ldg(b + tn);
    __syncthreads();                        // all sIn reads done before reuse
    float* sH = reinterpret_cast<float*>(sIn);   // 32 x 128 h2 tile (16 KB)
    #pragma unroll
    for (int m = 0; m < 16; m++)
        sH[(half * 16 + m) * DIM + tn] = fmaxf(acc[m] + bias, 0.f);
    __syncthreads();

    if (threadIdx.x < TILE_M * OUTD) {      // 160 threads: (row, out_col)
        int r = threadIdx.x / OUTD;
        int j = threadIdx.x % OUTD;
        float s0 = __ldg(bp + j), s1 = 0.f, s2 = 0.f, s3 = 0.f;
        const float* hrow = sH + r * DIM;
        #pragma unroll 8
        for (int n = 0; n < DIM; n += 4) {
            s0 = fmaf(hrow[n + 0], __ldg(Wp + (n + 0) * OUTD + j), s0);
            s1 = fmaf(hrow[n + 1], __ldg(Wp + (n + 1) * OUTD + j), s1);
            s2 = fmaf(hrow[n + 2], __ldg(Wp + (n + 2) * OUTD + j), s2);
            s3 = fmaf(hrow[n + 3], __ldg(Wp + (n + 3) * OUTD + j), s3);
        }
        out[(size_t)(row0 + r) * OUTD + j] = (s0 + s1) + (s2 + s3);
    }
}

// ---------------- launch (kernel launches ONLY; pure function of pointers) ----
extern "C" void kernel_launch(void* const* d_in, const int* in_sizes, int n_in,
                              void* d_out, int out_size)
{
    (void)in_sizes; (void)n_in; (void)out_size;   // fixed-shape problem

    const float* x   = (const float*)d_in[0];
    const int* edges = (const int*)  d_in[1];
    const float* W1  = (const float*)d_in[2];
    const float* b1  = (const float*)d_in[3];
    const float* W2  = (const float*)d_in[4];
    const float* b2  = (const float*)d_in[5];
    const float* Wp  = (const float*)d_in[6];
    const float* bp  = (const float*)d_in[7];
    float* out = (float*)d_out;

    const int* src = edges;                 // edges[0, :]
    const int* tgt = edges + N_EDGES;       // edges[1, :]

    const int zeroBlocks    = (N_NODES * D4 + 255) / 256;        // 12500
    const int scatterBlocks = (N_EDGES * 32 + 255) / 256;        // 200000
    const int gemmBlocks    = N_NODES / TILE_M;                  // 3125 exact

    zero_kernel<<<zeroBlocks, 256>>>();
    scatter_kernel<true ><<<scatterBlocks, 256>>>((const float4*)x, src, tgt);
    invcnt_kernel<<<(N_NODES + 255) / 256, 256>>>();
    gemm_relu_kernel<<<gemmBlocks, 256>>>((const float4*)x, W1, b1);
    scatter_kernel<false><<<scatterBlocks, 256>>>((const float4*)x, src, tgt);
    gemm_proj_kernel<<<gemmBlocks, 256>>>(W2, b2, Wp, bp, out);
}

// round 11
// speedup vs baseline: 1.1826x; 1.1826x over previous
#include <cuda_runtime.h>

// Fixed problem shape — kernel_launch is a pure function of the data pointers.
#define N_NODES 100000
#define N_EDGES 1600000
#define DIM     128
#define D4      32          // DIM/4
#define TILE_M  32
#define KCHUNK  32          // K rows of W staged per smem chunk (16 KB)
#define OUTD    5
#define SCAN_T  1024
#define CHUNK   98          // ceil(N_NODES / SCAN_T)

// ---------------- scratch (device globals; referenced ONLY in device code!) ----
// Passing these symbols as host-side kernel args would pass the HOST shadow
// (reachable via ATS on GB300) -> wrong buffer. Device-code refs only.
__device__ __align__(16) float g_in [(size_t)N_NODES * DIM];  // fused gemm input
__device__ __align__(16) float g_h1 [(size_t)N_NODES * DIM];  // layer-1 output
__device__ int g_cnt[N_NODES];          // degree histogram
__device__ int g_off[N_NODES + 1];      // CSR row offsets (by target)
__device__ int g_cur[N_NODES];          // fill cursors
__device__ int g_csr[N_EDGES];          // src ids grouped by target

// ---------------- zero degree histogram ----------------
__global__ void __launch_bounds__(256) zero_cnt_kernel() {
    int i = blockIdx.x * 256 + threadIdx.x;
    if (i < N_NODES) g_cnt[i] = 0;
}

// ---------------- degree histogram over targets ----------------
__global__ void __launch_bounds__(256) hist_kernel(const int* __restrict__ tgt) {
    int e = blockIdx.x * 256 + threadIdx.x;
    if (e < N_EDGES) atomicAdd(&g_cnt[__ldg(tgt + e)], 1);
}

// ---------------- one-block exclusive scan -> g_off, g_cur ----------------
__global__ void __launch_bounds__(SCAN_T) scan_kernel() {
    __shared__ int ssum[SCAN_T];
    int t  = threadIdx.x;
    int lo = t * CHUNK;
    int hi = lo + CHUNK; if (hi > N_NODES) hi = N_NODES;
    int s = 0;
    for (int i = lo; i < hi; i++) s += g_cnt[i];
    ssum[t] = s;
    __syncthreads();
    // Hillis-Steele inclusive scan (read-old / sync / write pattern)
    for (int d = 1; d < SCAN_T; d <<= 1) {
        int other = (t >= d) ? ssum[t - d] : 0;
        __syncthreads();
        ssum[t] += other;
        __syncthreads();
    }
    int run = ssum[t] - s;                 // exclusive prefix of this chunk
    for (int i = lo; i < hi; i++) {
        int c = g_cnt[i];
        g_off[i] = run;
        g_cur[i] = run;
        run += c;
    }
    if (t == SCAN_T - 1) g_off[N_NODES] = ssum[SCAN_T - 1];   // = N_EDGES
}

// ---------------- permute src ids into CSR order ----------------
__global__ void __launch_bounds__(256) fill_kernel(
    const int* __restrict__ src, const int* __restrict__ tgt) {
    int e = blockIdx.x * 256 + threadIdx.x;
    if (e < N_EDGES) {
        int p = atomicAdd(&g_cur[__ldg(tgt + e)], 1);
        g_csr[p] = __ldg(src + e);
    }
}

// ---------------- gather + mean + residual, fused into GEMM input ----------
// One warp per node, lane owns float4 column c. g_in[n] = base[n] + mean(agg).
// LAYER==1: base/feat = x (param). LAYER==2: base/feat = g_h1.
template <int LAYER>
__global__ void __launch_bounds__(256) gather_kernel(const float4* __restrict__ xfeat)
{
    int w    = (blockIdx.x * 256 + threadIdx.x) >> 5;
    int lane = threadIdx.x & 31;
    if (w >= N_NODES) return;

    const float4* feat = (LAYER == 1) ? xfeat
                                      : reinterpret_cast<const float4*>(g_h1);
    int beg = g_off[w];
    int end = g_off[w + 1];

    float4 a0 = make_float4(0.f,0.f,0.f,0.f), a1 = a0, a2 = a0, a3 = a0;
    int i = beg;
    for (; i + 4 <= end; i += 4) {                 // MLP=4 unrolled body
        int s0 = __ldg(g_csr + i + 0);
        int s1 = __ldg(g_csr + i + 1);
        int s2 = __ldg(g_csr + i + 2);
        int s3 = __ldg(g_csr + i + 3);
        float4 v0 = feat[s0 * D4 + lane];
        float4 v1 = feat[s1 * D4 + lane];
        float4 v2 = feat[s2 * D4 + lane];
        float4 v3 = feat[s3 * D4 + lane];
        a0.x += v0.x; a0.y += v0.y; a0.z += v0.z; a0.w += v0.w;
        a1.x += v1.x; a1.y += v1.y; a1.z += v1.z; a1.w += v1.w;
        a2.x += v2.x; a2.y += v2.y; a2.z += v2.z; a2.w += v2.w;
        a3.x += v3.x; a3.y += v3.y; a3.z += v3.z; a3.w += v3.w;
    }
    for (; i < end; i++) {
        float4 v = feat[__ldg(g_csr + i) * D4 + lane];
        a0.x += v.x; a0.y += v.y; a0.z += v.z; a0.w += v.w;
    }
    float4 sum = make_float4((a0.x + a1.x) + (a2.x + a3.x),
                             (a0.y + a1.y) + (a2.y + a3.y),
                             (a0.z + a1.z) + (a2.z + a3.z),
                             (a0.w + a1.w) + (a2.w + a3.w));

    int d = end - beg;
    float inv = 1.0f / (float)(d < 1 ? 1 : d);
    float4 xv = feat[(size_t)w * D4 + lane];       // residual base = same array
    reinterpret_cast<float4*>(g_in)[(size_t)w * D4 + lane] =
        make_float4(fmaf(sum.x, inv, xv.x), fmaf(sum.y, inv, xv.y),
                    fmaf(sum.z, inv, xv.z), fmaf(sum.w, inv, xv.w));
}

// ---------------- GEMM layer 1: g_h1 = relu(g_in @ W1 + b1) ----------------
__global__ void __launch_bounds__(256) gemm_relu_kernel(
    const float*  __restrict__ W,
    const float*  __restrict__ b)
{
    __shared__ float  sW[KCHUNK * DIM];      // 16 KB
    __shared__ float4 sIn[TILE_M * D4];      // 16 KB

    const float4* gin = reinterpret_cast<const float4*>(g_in);
    int row0 = blockIdx.x * TILE_M;

    #pragma unroll
    for (int i = threadIdx.x; i < TILE_M * D4; i += 256)
        sIn[i] = gin[(size_t)row0 * D4 + i];

    int tn   = threadIdx.x & 127;
    int half = threadIdx.x >> 7;
    float acc[16];
    #pragma unroll
    for (int m = 0; m < 16; m++) acc[m] = 0.f;

    float4* sW4 = reinterpret_cast<float4*>(sW);
    #pragma unroll 1
    for (int kc = 0; kc < DIM / KCHUNK; kc++) {
        __syncthreads();
        const float4* Wsrc = reinterpret_cast<const float4*>(W + kc * KCHUNK * DIM);
        #pragma unroll
        for (int i = threadIdx.x; i < KCHUNK * D4; i += 256) sW4[i] = Wsrc[i];
        __syncthreads();

        #pragma unroll 4
        for (int k4 = 0; k4 < KCHUNK / 4; k4++) {
            float w0 = sW[(k4 * 4 + 0) * DIM + tn];
            float w1 = sW[(k4 * 4 + 1) * DIM + tn];
            float w2 = sW[(k4 * 4 + 2) * DIM + tn];
            float w3 = sW[(k4 * 4 + 3) * DIM + tn];
            #pragma unroll
            for (int m = 0; m < 16; m++) {
                float4 xv = sIn[(half * 16 + m) * D4 + kc * (KCHUNK / 4) + k4];
                acc[m] = fmaf(xv.x, w0, acc[m]);
                acc[m] = fmaf(xv.y, w1, acc[m]);
                acc[m] = fmaf(xv.z, w2, acc[m]);
                acc[m] = fmaf(xv.w, w3, acc[m]);
            }
        }
    }

    float bias = __ldg(b + tn);
    #pragma unroll
    for (int m = 0; m < 16; m++) {
        int node = row0 + half * 16 + m;
        g_h1[(size_t)node * DIM + tn] = fmaxf(acc[m] + bias, 0.f);
    }
}

// ---------------- GEMM layer 2 fused with projection ----------------
// h2 = relu(g_in @ W2 + b2) kept in smem; out = h2 @ Wp + bp.
__global__ void __launch_bounds__(256) gemm_proj_kernel(
    const float*  __restrict__ W,
    const float*  __restrict__ b,
    const float*  __restrict__ Wp,
    const float*  __restrict__ bp,
    float*        __restrict__ out)
{
    __shared__ float  sW[KCHUNK * DIM];      // 16 KB
    __shared__ float4 sIn[TILE_M * D4];      // 16 KB (reused as h2 tile)

    const float4* gin = reinterpret_cast<const float4*>(g_in);
    int row0 = blockIdx.x * TILE_M;

    #pragma unroll
    for (int i = threadIdx.x; i < TILE_M * D4; i += 256)
        sIn[i] = gin[(size_t)row0 * D4 + i];

    int tn   = threadIdx.x & 127;
    int half = threadIdx.x >> 7;
    float acc[16];
    #pragma unroll
    for (int m = 0; m < 16; m++) acc[m] = 0.f;

    float4* sW4 = reinterpret_cast<float4*>(sW);
    #pragma unroll 1
    for (int kc = 0; kc < DIM / KCHUNK; kc++) {
        __syncthreads();
        const float4* Wsrc = reinterpret_cast<const float4*>(W + kc * KCHUNK * DIM);
        #pragma unroll
        for (int i = threadIdx.x; i < KCHUNK * D4; i += 256) sW4[i] = Wsrc[i];
        __syncthreads();

        #pragma unroll 4
        for (int k4 = 0; k4 < KCHUNK / 4; k4++) {
            float w0 = sW[(k4 * 4 + 0) * DIM + tn];
            float w1 = sW[(k4 * 4 + 1) * DIM + tn];
            float w2 = sW[(k4 * 4 + 2) * DIM + tn];
            float w3 = sW[(k4 * 4 + 3) * DIM + tn];
            #pragma unroll
            for (int m = 0; m < 16; m++) {
                float4 xv = sIn[(half * 16 + m) * D4 + kc * (KCHUNK / 4) + k4];
                acc[m] = fmaf(xv.x, w0, acc[m]);
                acc[m] = fmaf(xv.y, w1, acc[m]);
                acc[m] = fmaf(xv.z, w2, acc[m]);
                acc[m] = fmaf(xv.w, w3, acc[m]);
            }
        }
    }

    float bias = __ldg(b + tn);
    __syncthreads();                        // all sIn reads done before reuse
    float* sH = reinterpret_cast<float*>(sIn);   // 32 x 128 h2 tile
    #pragma unroll
    for (int m = 0; m < 16; m++)
        sH[(half * 16 + m) * DIM + tn] = fmaxf(acc[m] + bias, 0.f);
    __syncthreads();

    if (threadIdx.x < TILE_M * OUTD) {      // 160 threads: (row, out_col)
        int r = threadIdx.x / OUTD;
        int j = threadIdx.x % OUTD;
        float s0 = __ldg(bp + j), s1 = 0.f, s2 = 0.f, s3 = 0.f;
        const float* hrow = sH + r * DIM;
        #pragma unroll 8
        for (int n = 0; n < DIM; n += 4) {
            s0 = fmaf(hrow[n + 0], __ldg(Wp + (n + 0) * OUTD + j), s0);
            s1 = fmaf(hrow[n + 1], __ldg(Wp + (n + 1) * OUTD + j), s1);
            s2 = fmaf(hrow[n + 2], __ldg(Wp + (n + 2) * OUTD + j), s2);
            s3 = fmaf(hrow[n + 3], __ldg(Wp + (n + 3) * OUTD + j), s3);
        }
        out[(size_t)(row0 + r) * OUTD + j] = (s0 + s1) + (s2 + s3);
    }
}

// ---------------- launch (kernel launches ONLY; pure function of pointers) ----
extern "C" void kernel_launch(void* const* d_in, const int* in_sizes, int n_in,
                              void* d_out, int out_size)
{
    (void)in_sizes; (void)n_in; (void)out_size;   // fixed-shape problem

    const float* x   = (const float*)d_in[0];
    const int* edges = (const int*)  d_in[1];
    const float* W1  = (const float*)d_in[2];
    const float* b1  = (const float*)d_in[3];
    const float* W2  = (const float*)d_in[4];
    const float* b2  = (const float*)d_in[5];
    const float* Wp  = (const float*)d_in[6];
    const float* bp  = (const float*)d_in[7];
    float* out = (float*)d_out;

    const int* src = edges;                 // edges[0, :]
    const int* tgt = edges + N_EDGES;       // edges[1, :]

    const int nodeBlocks   = (N_NODES + 255) / 256;              // 391
    const int edgeBlocks   = (N_EDGES + 255) / 256;              // 6250
    const int gatherBlocks = (N_NODES * 32 + 255) / 256;         // 12500
    const int gemmBlocks   = N_NODES / TILE_M;                   // 3125 exact

    zero_cnt_kernel<<<nodeBlocks, 256>>>();
    hist_kernel<<<edgeBlocks, 256>>>(tgt);
    scan_kernel<<<1, SCAN_T>>>();
    fill_kernel<<<edgeBlocks, 256>>>(src, tgt);

    gather_kernel<1><<<gatherBlocks, 256>>>((const float4*)x);
    gemm_relu_kernel<<<gemmBlocks, 256>>>(W1, b1);
    gather_kernel<2><<<gatherBlocks, 256>>>((const float4*)x);
    gemm_proj_kernel<<<gemmBlocks, 256>>>(W2, b2, Wp, bp, out);
}

// round 12
// speedup vs baseline: 1.3181x; 1.1146x over previous
#include <cuda_runtime.h>

// Fixed problem shape — kernel_launch is a pure function of the data pointers.
#define N_NODES 100000
#define N_EDGES 1600000
#define DIM     128
#define D4      32
#define TILE_M  32          // nodes per block
#define KCHUNK  32          // K rows of W staged per smem chunk
#define OUTD    5
#define SA_S    36          // sA row stride in words (padded, 16B-aligned)
#define SCAN_T  1024
#define CHUNK   98          // ceil(N_NODES / SCAN_T)

// ---------------- scratch (device globals; referenced ONLY in device code!) ----
// Passing these symbols as host-side kernel args would pass the HOST shadow
// (reachable via ATS on GB300) -> wrong buffer. Device-code refs only.
__device__ __align__(16) float g_h1 [(size_t)N_NODES * DIM];  // layer-1 output
__device__ int g_cnt[N_NODES];          // degree histogram
__device__ int g_off[N_NODES + 1];      // CSR row offsets (by target)
__device__ int g_cur[N_NODES];          // fill cursors
__device__ int g_csr[N_EDGES];          // src ids grouped by target

// ---------------- zero degree histogram ----------------
__global__ void __launch_bounds__(256) zero_cnt_kernel() {
    int i = blockIdx.x * 256 + threadIdx.x;
    if (i < N_NODES) g_cnt[i] = 0;
}

// ---------------- degree histogram over targets ----------------
__global__ void __launch_bounds__(256) hist_kernel(const int* __restrict__ tgt) {
    int e = blockIdx.x * 256 + threadIdx.x;
    if (e < N_EDGES) atomicAdd(&g_cnt[__ldg(tgt + e)], 1);
}

// ---------------- one-block exclusive scan -> g_off, g_cur ----------------
__global__ void __launch_bounds__(SCAN_T) scan_kernel() {
    __shared__ int ssum[SCAN_T];
    int t  = threadIdx.x;
    int lo = t * CHUNK;
    int hi = lo + CHUNK; if (hi > N_NODES) hi = N_NODES;
    int s = 0;
    for (int i = lo; i < hi; i++) s += g_cnt[i];
    ssum[t] = s;
    __syncthreads();
    for (int d = 1; d < SCAN_T; d <<= 1) {
        int other = (t >= d) ? ssum[t - d] : 0;
        __syncthreads();
        ssum[t] += other;
        __syncthreads();
    }
    int run = ssum[t] - s;                 // exclusive prefix of this chunk
    for (int i = lo; i < hi; i++) {
        int c = g_cnt[i];
        g_off[i] = run;
        g_cur[i] = run;
        run += c;
    }
    if (t == SCAN_T - 1) g_off[N_NODES] = ssum[SCAN_T - 1];
}

// ---------------- permute src ids into CSR order ----------------
__global__ void __launch_bounds__(256) fill_kernel(
    const int* __restrict__ src, const int* __restrict__ tgt) {
    int e = blockIdx.x * 256 + threadIdx.x;
    if (e < N_EDGES) {
        int p = atomicAdd(&g_cur[__ldg(tgt + e)], 1);
        g_csr[p] = __ldg(src + e);
    }
}

// ================= fused layer: gather + mean + residual + GEMM ==============
// Block: 256 threads, 32 nodes, 128 output cols.
//   Phase 1: warp w gathers nodes 4w..4w+3 (lane owns 4 scalar k's, k=lane+32c)
//            into sA[k][m] (transposed, stride SA_S).
//   Phase 2: register-tiled GEMM: warp tile 16m x 32n, thread tile 4x4.
// LAYER==1: feat = x (param), epilogue writes relu(..) to g_h1.
// LAYER==2: feat = g_h1, epilogue keeps relu(..) in smem and projects to out.
template <int LAYER>
__global__ void __launch_bounds__(256) fused_layer_kernel(
    const float* __restrict__ xfeat,
    const float* __restrict__ W,
    const float* __restrict__ b,
    const float* __restrict__ Wp,
    const float* __restrict__ bp,
    float*       __restrict__ out)
{
    __shared__ __align__(16) float sA[DIM * SA_S];     // 18 KB, [k][m]
    __shared__ __align__(16) float sW[KCHUNK * DIM];   // 16 KB, [k][n] (reused as h2)

    const float* feat = (LAYER == 1) ? xfeat : (const float*)g_h1;
    int row0 = blockIdx.x * TILE_M;
    int lane = threadIdx.x & 31;
    int w    = threadIdx.x >> 5;          // warp 0..7

    // ---------- phase 1: gather 4 nodes per warp ----------
    #pragma unroll 1
    for (int j = 0; j < 4; j++) {
        int m    = w * 4 + j;             // local node index 0..31
        int node = row0 + m;
        int beg  = g_off[node];
        int end  = g_off[node + 1];

        float a0 = 0.f, a1 = 0.f, a2 = 0.f, a3 = 0.f;
        float b0 = 0.f, b1 = 0.f, b2 = 0.f, b3 = 0.f;
        int i = beg;
        for (; i + 2 <= end; i += 2) {    // 8 loads in flight
            const float* r0 = feat + (size_t)__ldg(g_csr + i)     * DIM;
            const float* r1 = feat + (size_t)__ldg(g_csr + i + 1) * DIM;
            a0 += __ldg(r0 + lane);      a1 += __ldg(r0 + lane + 32);
            a2 += __ldg(r0 + lane + 64); a3 += __ldg(r0 + lane + 96);
            b0 += __ldg(r1 + lane);      b1 += __ldg(r1 + lane + 32);
            b2 += __ldg(r1 + lane + 64); b3 += __ldg(r1 + lane + 96);
        }
        if (i < end) {
            const float* r0 = feat + (size_t)__ldg(g_csr + i) * DIM;
            a0 += __ldg(r0 + lane);      a1 += __ldg(r0 + lane + 32);
            a2 += __ldg(r0 + lane + 64); a3 += __ldg(r0 + lane + 96);
        }
        a0 += b0; a1 += b1; a2 += b2; a3 += b3;

        int d = end - beg;
        float inv = 1.0f / (float)(d < 1 ? 1 : d);
        const float* base = feat + (size_t)node * DIM;
        sA[(lane     ) * SA_S + m] = fmaf(a0, inv, __ldg(base + lane     ));
        sA[(lane + 32) * SA_S + m] = fmaf(a1, inv, __ldg(base + lane + 32));
        sA[(lane + 64) * SA_S + m] = fmaf(a2, inv, __ldg(base + lane + 64));
        sA[(lane + 96) * SA_S + m] = fmaf(a3, inv, __ldg(base + lane + 96));
    }

    // ---------- phase 2: GEMM, warp tile 16m x 32n, thread 4x4 ----------
    int mg = lane >> 3;                   // 0..3
    int ng = lane & 7;                    // 0..7
    int wm = w & 1;                       // m half
    int wn = w >> 1;                      // n quarter
    int mbase = wm * 16 + mg * 4;
    int nbase = wn * 32 + ng * 4;

    float acc[4][4];
    #pragma unroll
    for (int ii = 0; ii < 4; ii++)
        #pragma unroll
        for (int jj = 0; jj < 4; jj++) acc[ii][jj] = 0.f;

    #pragma unroll 1
    for (int kc = 0; kc < DIM / KCHUNK; kc++) {
        __syncthreads();                  // sA ready (kc=0) / sW reuse safe
        const float4* Wsrc = reinterpret_cast<const float4*>(W + kc * KCHUNK * DIM);
        float4* sW4 = reinterpret_cast<float4*>(sW);
        #pragma unroll
        for (int i = threadIdx.x; i < KCHUNK * D4; i += 256) sW4[i] = Wsrc[i];
        __syncthreads();

        const float* aptr = sA + (kc * KCHUNK) * SA_S + mbase;
        const float* wptr = sW + nbase;
        #pragma unroll 4
        for (int k = 0; k < KCHUNK; k++) {
            float4 av = *reinterpret_cast<const float4*>(aptr);
            float4 wv = *reinterpret_cast<const float4*>(wptr);
            acc[0][0] = fmaf(av.x, wv.x, acc[0][0]);
            acc[0][1] = fmaf(av.x, wv.y, acc[0][1]);
            acc[0][2] = fmaf(av.x, wv.z, acc[0][2]);
            acc[0][3] = fmaf(av.x, wv.w, acc[0][3]);
            acc[1][0] = fmaf(av.y, wv.x, acc[1][0]);
            acc[1][1] = fmaf(av.y, wv.y, acc[1][1]);
            acc[1][2] = fmaf(av.y, wv.z, acc[1][2]);
            acc[1][3] = fmaf(av.y, wv.w, acc[1][3]);
            acc[2][0] = fmaf(av.z, wv.x, acc[2][0]);
            acc[2][1] = fmaf(av.z, wv.y, acc[2][1]);
            acc[2][2] = fmaf(av.z, wv.z, acc[2][2]);
            acc[2][3] = fmaf(av.z, wv.w, acc[2][3]);
            acc[3][0] = fmaf(av.w, wv.x, acc[3][0]);
            acc[3][1] = fmaf(av.w, wv.y, acc[3][1]);
            acc[3][2] = fmaf(av.w, wv.z, acc[3][2]);
            acc[3][3] = fmaf(av.w, wv.w, acc[3][3]);
            aptr += SA_S;
            wptr += DIM;
        }
    }

    float4 bv = *reinterpret_cast<const float4*>(b + nbase);

    if (LAYER == 1) {
        #pragma unroll
        for (int ii = 0; ii < 4; ii++) {
            int node = row0 + mbase + ii;
            float4 h = make_float4(fmaxf(acc[ii][0] + bv.x, 0.f),
                                   fmaxf(acc[ii][1] + bv.y, 0.f),
                                   fmaxf(acc[ii][2] + bv.z, 0.f),
                                   fmaxf(acc[ii][3] + bv.w, 0.f));
            *reinterpret_cast<float4*>(g_h1 + (size_t)node * DIM + nbase) = h;
        }
    } else {
        __syncthreads();                  // all sW reads done; reuse as h2 tile
        float* sH = sW;                   // [32][128]
        #pragma unroll
        for (int ii = 0; ii < 4; ii++) {
            int m = mbase + ii;
            float4 h = make_float4(fmaxf(acc[ii][0] + bv.x, 0.f),
                                   fmaxf(acc[ii][1] + bv.y, 0.f),
                                   fmaxf(acc[ii][2] + bv.z, 0.f),
                                   fmaxf(acc[ii][3] + bv.w, 0.f));
            *reinterpret_cast<float4*>(sH + m * DIM + nbase) = h;
        }
        __syncthreads();

        if (threadIdx.x < TILE_M * OUTD) {    // 160 threads: (row, out col)
            int r = threadIdx.x / OUTD;
            int jj = threadIdx.x % OUTD;
            float s0 = __ldg(bp + jj), s1 = 0.f, s2 = 0.f, s3 = 0.f;
            const float* hrow = sH + r * DIM;
            #pragma unroll 8
            for (int n = 0; n < DIM; n += 4) {
                s0 = fmaf(hrow[n + 0], __ldg(Wp + (n + 0) * OUTD + jj), s0);
                s1 = fmaf(hrow[n + 1], __ldg(Wp + (n + 1) * OUTD + jj), s1);
                s2 = fmaf(hrow[n + 2], __ldg(Wp + (n + 2) * OUTD + jj), s2);
                s3 = fmaf(hrow[n + 3], __ldg(Wp + (n + 3) * OUTD + jj), s3);
            }
            out[(size_t)(row0 + r) * OUTD + jj] = (s0 + s1) + (s2 + s3);
        }
    }
}

// ---------------- launch (kernel launches ONLY; pure function of pointers) ----
extern "C" void kernel_launch(void* const* d_in, const int* in_sizes, int n_in,
                              void* d_out, int out_size)
{
    (void)in_sizes; (void)n_in; (void)out_size;   // fixed-shape problem

    const float* x   = (const float*)d_in[0];
    const int* edges = (const int*)  d_in[1];
    const float* W1  = (const float*)d_in[2];
    const float* b1  = (const float*)d_in[3];
    const float* W2  = (const float*)d_in[4];
    const float* b2  = (const float*)d_in[5];
    const float* Wp  = (const float*)d_in[6];
    const float* bp  = (const float*)d_in[7];
    float* out = (float*)d_out;

    const int* src = edges;                 // edges[0, :]
    const int* tgt = edges + N_EDGES;       // edges[1, :]

    const int nodeBlocks = (N_NODES + 255) / 256;   // 391
    const int edgeBlocks = (N_EDGES + 255) / 256;   // 6250
    const int gemmBlocks = N_NODES / TILE_M;        // 3125 exact

    zero_cnt_kernel<<<nodeBlocks, 256>>>();
    hist_kernel<<<edgeBlocks, 256>>>(tgt);
    scan_kernel<<<1, SCAN_T>>>();
    fill_kernel<<<edgeBlocks, 256>>>(src, tgt);

    fused_layer_kernel<1><<<gemmBlocks, 256>>>(x, W1, b1, nullptr, nullptr, nullptr);
    fused_layer_kernel<2><<<gemmBlocks, 256>>>(x, W2, b2, Wp, bp, out);
}